// round 2
// baseline (speedup 1.0000x reference)
#include <cuda_runtime.h>
#include <cuda_bf16.h>
#include <cstdint>
#include <cstdio>

// ---------------------------------------------------------------------------
// Problem constants (fixed by the dataset):
//   N=1024 queries, B=4, D=384, NH=8, HD=48, HALF=24, NF=8, L=4, NS=7
//   total cells per batch = 64*64+32*32+16*16+8*8 = 5440
//   K (keys per query) = L*NS*NS = 196
// ---------------------------------------------------------------------------

#define Dm 384
#define NHm 8
#define HDm 48
#define HALFm 24
#define Lm 4
#define NSm 7
#define NKEY 196
#define MAXQ 1024
#define MAXROWS 21760   // B * total

// ---------------- device scratch (static allocation; no cudaMalloc) --------
__device__ float g_xn[MAXQ * Dm];        // layernorm output
__device__ float g_q[MAXQ * Dm];         // q projection
__device__ float g_qr[MAXQ * Dm];        // rotated q
__device__ float g_attn[MAXQ * Dm];      // attention output
__device__ float g_kv[(size_t)MAXROWS * 2 * Dm];  // projected kv maps (66.8 MB)

// ---------------------------------------------------------------------------
// LayerNorm: one block per query row, 384 threads
// ---------------------------------------------------------------------------
__global__ void ln_kernel(const float* __restrict__ x,
                          const float* __restrict__ w,
                          const float* __restrict__ b,
                          float* __restrict__ y) {
    int n = blockIdx.x;
    int d = threadIdx.x;            // 0..383
    float v = x[n * Dm + d];
    float s = v, s2 = v * v;
    #pragma unroll
    for (int o = 16; o; o >>= 1) {
        s  += __shfl_xor_sync(0xFFFFFFFFu, s,  o);
        s2 += __shfl_xor_sync(0xFFFFFFFFu, s2, o);
    }
    __shared__ float sw[12], sw2[12];
    int wid = d >> 5, lane = d & 31;
    if (lane == 0) { sw[wid] = s; sw2[wid] = s2; }
    __syncthreads();
    if (d == 0) {
        float a = 0.f, a2 = 0.f;
        #pragma unroll
        for (int i = 0; i < 12; i++) { a += sw[i]; a2 += sw2[i]; }
        sw[0] = a; sw2[0] = a2;
    }
    __syncthreads();
    float mu  = sw[0] * (1.f / Dm);
    float var = sw2[0] * (1.f / Dm) - mu * mu;
    float r = rsqrtf(var + 1e-5f);
    y[n * Dm + d] = (v - mu) * r * w[d] + b[d];
}

// ---------------------------------------------------------------------------
// Generic fp32 GEMM:  C[m,n] = sum_k A[m,k] * W[n,k]  (+ R[m,n] if R != null)
// A: MxK row-major, W: NxK row-major.  BM=128, BN=64, BK=16, 256 threads.
// Requires: N % 64 == 0, K % 16 == 0. M guarded.
// ---------------------------------------------------------------------------
__global__ void __launch_bounds__(256)
gemm_nt_kernel(const float* __restrict__ A, const float* __restrict__ W,
               const float* __restrict__ R, float* __restrict__ C,
               int M, int N, int K) {
    __shared__ float As[16][132];
    __shared__ float Ws[16][68];
    const int tid = threadIdx.x;
    const int bm = blockIdx.y * 128;
    const int bn = blockIdx.x * 64;
    const int tx = tid & 15;   // column group (x4)
    const int ty = tid >> 4;   // row group   (x8)

    float acc[8][4];
    #pragma unroll
    for (int i = 0; i < 8; i++)
        #pragma unroll
        for (int j = 0; j < 4; j++) acc[i][j] = 0.f;

    for (int k0 = 0; k0 < K; k0 += 16) {
        // load A tile (128 x 16), 512 float4 -> 2 per thread
        #pragma unroll
        for (int i = 0; i < 2; i++) {
            int idx = tid + i * 256;
            int row = idx >> 2;
            int c4  = (idx & 3) << 2;
            float4 v = make_float4(0.f, 0.f, 0.f, 0.f);
            int gr = bm + row;
            if (gr < M) v = *(const float4*)(A + (size_t)gr * K + k0 + c4);
            As[c4 + 0][row] = v.x; As[c4 + 1][row] = v.y;
            As[c4 + 2][row] = v.z; As[c4 + 3][row] = v.w;
        }
        // load W tile (64 x 16), 256 float4 -> 1 per thread
        {
            int row = tid >> 2;
            int c4  = (tid & 3) << 2;
            float4 v = *(const float4*)(W + (size_t)(bn + row) * K + k0 + c4);
            Ws[c4 + 0][row] = v.x; Ws[c4 + 1][row] = v.y;
            Ws[c4 + 2][row] = v.z; Ws[c4 + 3][row] = v.w;
        }
        __syncthreads();
        #pragma unroll
        for (int kk = 0; kk < 16; kk++) {
            float4 a0 = *(const float4*)&As[kk][ty * 8];
            float4 a1 = *(const float4*)&As[kk][ty * 8 + 4];
            float4 b0 = *(const float4*)&Ws[kk][tx * 4];
            float a[8] = {a0.x, a0.y, a0.z, a0.w, a1.x, a1.y, a1.z, a1.w};
            float bb[4] = {b0.x, b0.y, b0.z, b0.w};
            #pragma unroll
            for (int i = 0; i < 8; i++)
                #pragma unroll
                for (int j = 0; j < 4; j++)
                    acc[i][j] = fmaf(a[i], bb[j], acc[i][j]);
        }
        __syncthreads();
    }

    #pragma unroll
    for (int i = 0; i < 8; i++) {
        int row = bm + ty * 8 + i;
        if (row >= M) continue;
        int col = bn + tx * 4;
        float4 o = make_float4(acc[i][0], acc[i][1], acc[i][2], acc[i][3]);
        if (R) {
            float4 r = *(const float4*)(R + (size_t)row * N + col);
            o.x += r.x; o.y += r.y; o.z += r.z; o.w += r.w;
        }
        *(float4*)(C + (size_t)row * N + col) = o;
    }
}

// ---------------------------------------------------------------------------
// RoPE for q: one block per query, 384 threads (one per output element)
// ---------------------------------------------------------------------------
__global__ void rope_q_kernel(const float* __restrict__ q,
                              const int* __restrict__ pos,
                              float* __restrict__ qr) {
    int n = blockIdx.x;
    int o = threadIdx.x;                 // 0..383
    int h = o / HDm;
    int d = o - h * HDm;
    int j = (d < HALFm) ? d : d - HALFm;
    float fqi = (float)pos[n * 4 + 1];
    float fqj = (float)pos[n * 4 + 2];
    float fql = (float)pos[n * 4 + 3];
    float ang;
    if (j < 8)       ang = fqi * exp10f(-(float)j * 0.125f);
    else if (j < 16) ang = fqj * exp10f(-(float)(j - 8) * 0.125f);
    else             ang = fql * exp10f((float)(j - 16) * 0.125f);
    float s, c;
    sincosf(ang, &s, &c);
    float x1 = q[n * Dm + h * HDm + j];
    float x2 = q[n * Dm + h * HDm + HALFm + j];
    qr[n * Dm + o] = (d < HALFm) ? (x1 * c - x2 * s) : (x1 * s + x2 * c);
}

// ---------------------------------------------------------------------------
// Attention: one block per query (256 threads = 8 warps, warp w = head w)
// smem: q(1.5K) + cos/sin(36.75K) + rowbase(0.77K) + scores(6.1K) ~= 46 KB
// ---------------------------------------------------------------------------
__global__ void __launch_bounds__(256)
attn_kernel(const float* __restrict__ qr,
            const int* __restrict__ pos,
            const int* __restrict__ shapes,
            const float* __restrict__ kv,
            float* __restrict__ attn_out,
            int total) {
    __shared__ float q_sh[Dm];
    __shared__ float cs_sh[NKEY][HALFm];
    __shared__ float ss_sh[NKEY][HALFm];
    __shared__ int   rb_sh[NKEY];
    __shared__ float sc_sh[NHm][NKEY];
    __shared__ int   ci_sh[Lm], cj_sh[Lm], Hs_sh[Lm], Ws_sh[Lm], offs_sh[Lm];

    const int n = blockIdx.x;
    const int t = threadIdx.x;

    for (int i = t; i < Dm; i += 256) q_sh[i] = qr[n * Dm + i];

    if (t == 0) {
        int qi = pos[n * 4 + 1], qj = pos[n * 4 + 2], ql = pos[n * 4 + 3];
        float Hq = (float)shapes[2 * ql];
        float Wq = (float)shapes[2 * ql + 1];
        int off = 0;
        #pragma unroll
        for (int l = 0; l < Lm; l++) {
            int H = shapes[2 * l], W = shapes[2 * l + 1];
            Hs_sh[l] = H; Ws_sh[l] = W; offs_sh[l] = off; off += H * W;
            ci_sh[l] = (int)floorf(((float)qi + 0.5f) * (float)H / Hq);
            cj_sh[l] = (int)floorf(((float)qj + 0.5f) * (float)W / Wq);
        }
    }
    __syncthreads();

    const int bq = pos[n * 4 + 0];
    if (t < NKEY) {
        int l  = t / 49;
        int r  = t - l * 49;
        int si = r / 7, sj = r - (r / 7) * 7;
        int H = Hs_sh[l], W = Ws_sh[l];
        int ii = ci_sh[l] + si - 3;
        int jj = cj_sh[l] + sj - 3;
        bool vld = (ii >= 0) && (ii < H) && (jj >= 0) && (jj < W);
        int iic = min(max(ii, 0), H - 1);
        int jjc = min(max(jj, 0), W - 1);
        rb_sh[t] = vld ? (bq * total + offs_sh[l] + iic * W + jjc) : -1;
        float fi = (float)iic, fj = (float)jjc, flv = (float)l;
        #pragma unroll
        for (int j = 0; j < 8; j++) {
            float s, c;
            sincosf(fi * exp10f(-(float)j * 0.125f), &s, &c);
            cs_sh[t][j] = c;      ss_sh[t][j] = s;
            sincosf(fj * exp10f(-(float)j * 0.125f), &s, &c);
            cs_sh[t][8 + j] = c;  ss_sh[t][8 + j] = s;
            sincosf(flv * exp10f((float)j * 0.125f), &s, &c);
            cs_sh[t][16 + j] = c; ss_sh[t][16 + j] = s;
        }
    }
    __syncthreads();

    const int h = t >> 5;          // warp id = head
    const int lane = t & 31;
    const float scale = rsqrtf((float)HDm);

    // ---- scores: each lane handles keys lane, lane+32, ...
    for (int k = lane; k < NKEY; k += 32) {
        int rb = rb_sh[k];
        float sc;
        if (rb >= 0) {
            const float* kp = kv + (size_t)rb * (2 * Dm) + h * HDm;
            sc = 0.f;
            #pragma unroll
            for (int j = 0; j < HALFm; j++) {
                float k1 = kp[j];
                float k2 = kp[HALFm + j];
                float c = cs_sh[k][j], s = ss_sh[k][j];
                float q1 = q_sh[h * HDm + j];
                float q2 = q_sh[h * HDm + HALFm + j];
                sc += (k1 * c - k2 * s) * q1 + (k1 * s + k2 * c) * q2;
            }
            sc *= scale;
        } else {
            sc = -1e30f;
        }
        sc_sh[h][k] = sc;
    }
    __syncwarp();

    // ---- softmax (per warp over 196 keys)
    float m = -1e30f;
    for (int k = lane; k < NKEY; k += 32) m = fmaxf(m, sc_sh[h][k]);
    #pragma unroll
    for (int o = 16; o; o >>= 1) m = fmaxf(m, __shfl_xor_sync(0xFFFFFFFFu, m, o));
    float lsum = 0.f;
    for (int k = lane; k < NKEY; k += 32) {
        float p = expf(sc_sh[h][k] - m);
        sc_sh[h][k] = p;
        lsum += p;
    }
    #pragma unroll
    for (int o = 16; o; o >>= 1) lsum += __shfl_xor_sync(0xFFFFFFFFu, lsum, o);
    __syncwarp();

    // ---- weighted V accumulation: lane owns dims {lane} and {lane+32 if <48}
    float acc0 = 0.f, acc1 = 0.f;
    for (int k = 0; k < NKEY; k++) {
        int rb = rb_sh[k];
        if (rb < 0) continue;
        float p = sc_sh[h][k];
        const float* vp = kv + (size_t)rb * (2 * Dm) + Dm + h * HDm;
        acc0 += p * vp[lane];
        if (lane < 16) acc1 += p * vp[32 + lane];
    }
    float inv = 1.f / lsum;
    attn_out[n * Dm + h * HDm + lane] = acc0 * inv;
    if (lane < 16)
        attn_out[n * Dm + h * HDm + 32 + lane] = acc1 * inv;
}

// ---------------------------------------------------------------------------
// kernel_launch
// Inputs (metadata order):
//  0 query (N,384) f32        1 query_positions_bijl (N,4) i32
//  2 query_batch_offsets i32  3 stacked_feature_maps (B,total,384) f32
//  4 level_spatial_shapes (4,2) i32
//  5 norm_weight f32          6 norm_bias f32
//  7 w_q (384,384) f32        8 w_kv (768,384) f32      9 w_out (384,384) f32
// output: (N,384) f32
// ---------------------------------------------------------------------------
extern "C" void kernel_launch(void* const* d_in, const int* in_sizes, int n_in,
                              void* d_out, int out_size) {
    const float* query  = (const float*)d_in[0];
    const int*   pos    = (const int*)d_in[1];
    const float* fm     = (const float*)d_in[3];
    const int*   shapes = (const int*)d_in[4];
    const float* nw     = (const float*)d_in[5];
    const float* nb     = (const float*)d_in[6];
    const float* w_q    = (const float*)d_in[7];
    const float* w_kv   = (const float*)d_in[8];
    const float* w_out  = (const float*)d_in[9];
    float* out = (float*)d_out;

    const int D  = Dm;
    const int NQ = in_sizes[0] / D;
    const int Bn = in_sizes[2] - 1;
    const int total = in_sizes[3] / (Bn * D);
    const int Mkv = Bn * total;

    float *xn, *qb, *qrp, *attn, *kvp;
    cudaGetSymbolAddress((void**)&xn,   g_xn);
    cudaGetSymbolAddress((void**)&qb,   g_q);
    cudaGetSymbolAddress((void**)&qrp,  g_qr);
    cudaGetSymbolAddress((void**)&attn, g_attn);
    cudaGetSymbolAddress((void**)&kvp,  g_kv);

    // 1. LayerNorm
    ln_kernel<<<NQ, Dm>>>(query, nw, nb, xn);

    // 2. q = xn @ w_q^T
    {
        dim3 grid(D / 64, (NQ + 127) / 128);
        gemm_nt_kernel<<<grid, 256>>>(xn, w_q, nullptr, qb, NQ, D, D);
    }

    // 3. RoPE on q
    rope_q_kernel<<<NQ, Dm>>>(qb, pos, qrp);

    // 4. kv_maps = fm @ w_kv^T  (big GEMM: Mkv x 768 x 384)
    {
        dim3 grid((2 * D) / 64, (Mkv + 127) / 128);
        gemm_nt_kernel<<<grid, 256>>>(fm, w_kv, nullptr, kvp, Mkv, 2 * D, D);
    }

    // 5. sparse neighborhood attention
    attn_kernel<<<NQ, 256>>>(qrp, pos, shapes, kvp, attn, total);

    // 6. out = attn @ w_out^T + residual
    {
        dim3 grid(D / 64, (NQ + 127) / 128);
        gemm_nt_kernel<<<grid, 256>>>(attn, w_out, query, out, NQ, D, D);
    }
}

// round 3
// speedup vs baseline: 2.7174x; 2.7174x over previous
#include <cuda_runtime.h>
#include <cuda_bf16.h>
#include <cstdint>

// ---------------------------------------------------------------------------
// Constants fixed by the dataset:
//   N=1024 queries, B=4, D=384, NH=8, HD=48, HALF=24, NF=8, L=4, NS=7
//   total cells per batch = 5440, K(keys/query) = 196
// ---------------------------------------------------------------------------
#define Dm 384
#define NHm 8
#define HDm 48
#define HALFm 24
#define Lm 4
#define NKEY 196
#define MAXQ 1024
#define MAXROWS 21760   // B * total

// ---------------- device scratch (static; no cudaMalloc) -------------------
__device__ float g_xn[MAXQ * Dm];                    // layernorm output
__device__ float g_q[MAXQ * Dm];                     // q projection
__device__ float g_qr[MAXQ * Dm];                    // rotated+scaled q
__device__ float g_attn[MAXQ * Dm];                  // attention output
__device__ float g_kv[(size_t)MAXROWS * 2 * Dm];     // raw projected kv (66.8MB)
__device__ float g_kh[(size_t)NHm * MAXROWS * HDm];  // rotated K head-major
__device__ float g_vh[(size_t)NHm * MAXROWS * HDm];  // V head-major

// ---------------------------------------------------------------------------
// LayerNorm: one block per query row, 384 threads
// ---------------------------------------------------------------------------
__global__ void ln_kernel(const float* __restrict__ x,
                          const float* __restrict__ w,
                          const float* __restrict__ b,
                          float* __restrict__ y) {
    int n = blockIdx.x;
    int d = threadIdx.x;
    float v = x[n * Dm + d];
    float s = v, s2 = v * v;
    #pragma unroll
    for (int o = 16; o; o >>= 1) {
        s  += __shfl_xor_sync(0xFFFFFFFFu, s,  o);
        s2 += __shfl_xor_sync(0xFFFFFFFFu, s2, o);
    }
    __shared__ float sw[12], sw2[12];
    int wid = d >> 5, lane = d & 31;
    if (lane == 0) { sw[wid] = s; sw2[wid] = s2; }
    __syncthreads();
    if (d == 0) {
        float a = 0.f, a2 = 0.f;
        #pragma unroll
        for (int i = 0; i < 12; i++) { a += sw[i]; a2 += sw2[i]; }
        sw[0] = a; sw2[0] = a2;
    }
    __syncthreads();
    float mu  = sw[0] * (1.f / Dm);
    float var = sw2[0] * (1.f / Dm) - mu * mu;
    float r = rsqrtf(var + 1e-5f);
    y[n * Dm + d] = (v - mu) * r * w[d] + b[d];
}

// ---------------------------------------------------------------------------
// tf32 tensor-core GEMM:  C[m,n] = sum_k A[m,k]*W[n,k]  (+R[m,n] if R!=null)
// CTA tile 128x64, K-step 32, 8 warps (warp tile 32x32), mma m16n8k8.
// Requires N%64==0, K%32==0; M guarded.
// ---------------------------------------------------------------------------
__device__ __forceinline__ uint32_t f2tf32(float x) {
    uint32_t u;
    asm("cvt.rna.tf32.f32 %0, %1;" : "=r"(u) : "f"(x));
    return u;
}

__global__ void __launch_bounds__(256)
gemm_tf32_kernel(const float* __restrict__ A, const float* __restrict__ W,
                 const float* __restrict__ R, float* __restrict__ C,
                 int M, int N, int K) {
    __shared__ uint32_t As[128][36];   // [row][k], pad 36 -> conflict-free frags
    __shared__ uint32_t Ws[64][36];    // [n][k]

    const int tid  = threadIdx.x;
    const int lane = tid & 31;
    const int warp = tid >> 5;
    const int wm   = warp >> 1;        // 0..3
    const int wn   = warp & 1;         // 0..1
    const int bm   = blockIdx.y * 128;
    const int bn   = blockIdx.x * 64;

    float d[2][4][4];
    #pragma unroll
    for (int mt = 0; mt < 2; mt++)
        #pragma unroll
        for (int nt = 0; nt < 4; nt++)
            #pragma unroll
            for (int i = 0; i < 4; i++) d[mt][nt][i] = 0.f;

    float4 pa[4], pb[2];

    // prefetch first tile
    #pragma unroll
    for (int i = 0; i < 4; i++) {
        int idx = tid + 256 * i;
        int row = idx >> 3, c4 = (idx & 7) << 2;
        int gr = bm + row;
        pa[i] = (gr < M) ? *(const float4*)(A + (size_t)gr * K + c4)
                         : make_float4(0.f, 0.f, 0.f, 0.f);
    }
    #pragma unroll
    for (int i = 0; i < 2; i++) {
        int idx = tid + 256 * i;
        int row = idx >> 3, c4 = (idx & 7) << 2;
        pb[i] = *(const float4*)(W + (size_t)(bn + row) * K + c4);
    }

    for (int k0 = 0; k0 < K; k0 += 32) {
        // store current tile to smem (convert to tf32)
        #pragma unroll
        for (int i = 0; i < 4; i++) {
            int idx = tid + 256 * i;
            int row = idx >> 3, c4 = (idx & 7) << 2;
            As[row][c4 + 0] = f2tf32(pa[i].x);
            As[row][c4 + 1] = f2tf32(pa[i].y);
            As[row][c4 + 2] = f2tf32(pa[i].z);
            As[row][c4 + 3] = f2tf32(pa[i].w);
        }
        #pragma unroll
        for (int i = 0; i < 2; i++) {
            int idx = tid + 256 * i;
            int row = idx >> 3, c4 = (idx & 7) << 2;
            Ws[row][c4 + 0] = f2tf32(pb[i].x);
            Ws[row][c4 + 1] = f2tf32(pb[i].y);
            Ws[row][c4 + 2] = f2tf32(pb[i].z);
            Ws[row][c4 + 3] = f2tf32(pb[i].w);
        }
        __syncthreads();

        // prefetch next tile
        if (k0 + 32 < K) {
            #pragma unroll
            for (int i = 0; i < 4; i++) {
                int idx = tid + 256 * i;
                int row = idx >> 3, c4 = (idx & 7) << 2;
                int gr = bm + row;
                pa[i] = (gr < M) ? *(const float4*)(A + (size_t)gr * K + k0 + 32 + c4)
                                 : make_float4(0.f, 0.f, 0.f, 0.f);
            }
            #pragma unroll
            for (int i = 0; i < 2; i++) {
                int idx = tid + 256 * i;
                int row = idx >> 3, c4 = (idx & 7) << 2;
                pb[i] = *(const float4*)(W + (size_t)(bn + row) * K + k0 + 32 + c4);
            }
        }

        // compute: 4 k8 steps
        #pragma unroll
        for (int ks = 0; ks < 4; ks++) {
            uint32_t af[2][4], bf[4][2];
            int c = ks * 8 + (lane & 3);
            #pragma unroll
            for (int mt = 0; mt < 2; mt++) {
                int r = wm * 32 + mt * 16 + (lane >> 2);
                af[mt][0] = As[r][c];
                af[mt][1] = As[r + 8][c];
                af[mt][2] = As[r][c + 4];
                af[mt][3] = As[r + 8][c + 4];
            }
            #pragma unroll
            for (int nt = 0; nt < 4; nt++) {
                int col = wn * 32 + nt * 8 + (lane >> 2);
                bf[nt][0] = Ws[col][c];
                bf[nt][1] = Ws[col][c + 4];
            }
            #pragma unroll
            for (int mt = 0; mt < 2; mt++)
                #pragma unroll
                for (int nt = 0; nt < 4; nt++)
                    asm volatile(
                        "mma.sync.aligned.m16n8k8.row.col.f32.tf32.tf32.f32 "
                        "{%0,%1,%2,%3}, {%4,%5,%6,%7}, {%8,%9}, {%0,%1,%2,%3};"
                        : "+f"(d[mt][nt][0]), "+f"(d[mt][nt][1]),
                          "+f"(d[mt][nt][2]), "+f"(d[mt][nt][3])
                        : "r"(af[mt][0]), "r"(af[mt][1]),
                          "r"(af[mt][2]), "r"(af[mt][3]),
                          "r"(bf[nt][0]), "r"(bf[nt][1]));
        }
        __syncthreads();
    }

    // epilogue
    #pragma unroll
    for (int mt = 0; mt < 2; mt++) {
        #pragma unroll
        for (int nt = 0; nt < 4; nt++) {
            int row0 = bm + wm * 32 + mt * 16 + (lane >> 2);
            int col  = bn + wn * 32 + nt * 8 + ((lane & 3) << 1);
            if (row0 < M) {
                float2 o = make_float2(d[mt][nt][0], d[mt][nt][1]);
                if (R) {
                    const float2 r = *(const float2*)(R + (size_t)row0 * N + col);
                    o.x += r.x; o.y += r.y;
                }
                *(float2*)(C + (size_t)row0 * N + col) = o;
            }
            int row1 = row0 + 8;
            if (row1 < M) {
                float2 o = make_float2(d[mt][nt][2], d[mt][nt][3]);
                if (R) {
                    const float2 r = *(const float2*)(R + (size_t)row1 * N + col);
                    o.x += r.x; o.y += r.y;
                }
                *(float2*)(C + (size_t)row1 * N + col) = o;
            }
        }
    }
}

// ---------------------------------------------------------------------------
// RoPE + scale for q: one block per query, 384 threads
// ---------------------------------------------------------------------------
__global__ void rope_q_kernel(const float* __restrict__ q,
                              const int* __restrict__ pos,
                              float* __restrict__ qr) {
    int n = blockIdx.x;
    int o = threadIdx.x;                 // 0..383
    int h = o / HDm;
    int d = o - h * HDm;
    int j = (d < HALFm) ? d : d - HALFm;
    float fqi = (float)pos[n * 4 + 1];
    float fqj = (float)pos[n * 4 + 2];
    float fql = (float)pos[n * 4 + 3];
    float ang;
    if (j < 8)       ang = fqi * exp10f(-(float)j * 0.125f);
    else if (j < 16) ang = fqj * exp10f(-(float)(j - 8) * 0.125f);
    else             ang = fql * exp10f((float)(j - 16) * 0.125f);
    float s, c;
    sincosf(ang, &s, &c);
    float x1 = q[n * Dm + h * HDm + j];
    float x2 = q[n * Dm + h * HDm + HALFm + j];
    const float scale = 0.14433756729740643f;   // 1/sqrt(48)
    float r = (d < HALFm) ? (x1 * c - x2 * s) : (x1 * s + x2 * c);
    qr[n * Dm + o] = r * scale;
}

// ---------------------------------------------------------------------------
// RoPE on K (per-cell, query independent) + relayout KV to head-major.
// One block per kv row, 384 threads.
// kh[h][row][48] = rotate(k), vh[h][row][48] = v
// ---------------------------------------------------------------------------
__global__ void rope_kv_kernel(const float* __restrict__ kv,
                               const int* __restrict__ shapes,
                               float* __restrict__ kh, float* __restrict__ vh,
                               int Mkv, int total) {
    __shared__ int sh_l, sh_i, sh_j;
    int r = blockIdx.x;
    int t = threadIdx.x;
    if (t == 0) {
        int c = r % total;
        int off = 0, l = 0, i = 0, j = 0;
        #pragma unroll
        for (int lv = 0; lv < Lm; lv++) {
            int H = shapes[2 * lv], W = shapes[2 * lv + 1];
            int sz = H * W;
            if (c >= off && c < off + sz) {
                l = lv; i = (c - off) / W; j = (c - off) - ((c - off) / W) * W;
            }
            off += sz;
        }
        sh_l = l; sh_i = i; sh_j = j;
    }
    __syncthreads();
    int h  = t / HDm;
    int dd = t - h * HDm;
    int jj = (dd < HALFm) ? dd : dd - HALFm;
    float fi = (float)sh_i, fj = (float)sh_j, fl = (float)sh_l;
    float ang;
    if (jj < 8)       ang = fi * exp10f(-(float)jj * 0.125f);
    else if (jj < 16) ang = fj * exp10f(-(float)(jj - 8) * 0.125f);
    else              ang = fl * exp10f((float)(jj - 16) * 0.125f);
    float s, c;
    sincosf(ang, &s, &c);
    const float* row = kv + (size_t)r * (2 * Dm);
    float k1 = row[h * HDm + jj];
    float k2 = row[h * HDm + HALFm + jj];
    float kr = (dd < HALFm) ? (k1 * c - k2 * s) : (k1 * s + k2 * c);
    size_t ob = ((size_t)h * Mkv + r) * HDm + dd;
    kh[ob] = kr;
    vh[ob] = row[Dm + t];
}

// ---------------------------------------------------------------------------
// Attention: one block per query, 8 warps (warp = head).
// 16-lane groups process 2 keys/iteration with coalesced float4 loads.
// ---------------------------------------------------------------------------
__global__ void __launch_bounds__(256)
attn_kernel(const float* __restrict__ qr,
            const int* __restrict__ pos,
            const int* __restrict__ shapes,
            const float* __restrict__ kh,
            const float* __restrict__ vh,
            float* __restrict__ attn_out,
            int total, int Mkv) {
    __shared__ float sc_sh[NHm][NKEY];
    __shared__ int   rb_sh[NKEY];
    __shared__ int   ci_sh[Lm], cj_sh[Lm], Hs_sh[Lm], Ws_sh[Lm], offs_sh[Lm];

    const int n = blockIdx.x;
    const int t = threadIdx.x;

    if (t == 0) {
        int qi = pos[n * 4 + 1], qj = pos[n * 4 + 2], ql = pos[n * 4 + 3];
        float Hq = (float)shapes[2 * ql];
        float Wq = (float)shapes[2 * ql + 1];
        int off = 0;
        #pragma unroll
        for (int l = 0; l < Lm; l++) {
            int H = shapes[2 * l], W = shapes[2 * l + 1];
            Hs_sh[l] = H; Ws_sh[l] = W; offs_sh[l] = off; off += H * W;
            ci_sh[l] = (int)floorf(((float)qi + 0.5f) * (float)H / Hq);
            cj_sh[l] = (int)floorf(((float)qj + 0.5f) * (float)W / Wq);
        }
    }
    __syncthreads();

    const int bq = pos[n * 4 + 0];
    if (t < NKEY) {
        int l  = t / 49;
        int rr = t - l * 49;
        int si = rr / 7, sj = rr - (rr / 7) * 7;
        int H = Hs_sh[l], W = Ws_sh[l];
        int ii = ci_sh[l] + si - 3;
        int jj = cj_sh[l] + sj - 3;
        bool vld = (ii >= 0) && (ii < H) && (jj >= 0) && (jj < W);
        rb_sh[t] = vld ? (bq * total + offs_sh[l] + ii * W + jj) : -1;
    }
    __syncthreads();

    const int h    = t >> 5;
    const int lane = t & 31;
    const int grp  = lane >> 4;      // 0 or 1
    const int p    = lane & 15;      // active if p < 12

    // q fragment: lane's float4 of the rotated, pre-scaled q
    float4 q4 = make_float4(0.f, 0.f, 0.f, 0.f);
    if (p < 12) q4 = *(const float4*)(qr + n * Dm + h * HDm + p * 4);

    // ---- scores
    for (int it = 0; it < NKEY / 2; ++it) {
        int k  = it * 2 + grp;
        int rb = rb_sh[k];
        float partial = 0.f;
        if (p < 12 && rb >= 0) {
            float4 kk = *(const float4*)(kh + ((size_t)h * Mkv + rb) * HDm + p * 4);
            partial = q4.x * kk.x + q4.y * kk.y + q4.z * kk.z + q4.w * kk.w;
        }
        partial += __shfl_xor_sync(0xFFFFFFFFu, partial, 8);
        partial += __shfl_xor_sync(0xFFFFFFFFu, partial, 4);
        partial += __shfl_xor_sync(0xFFFFFFFFu, partial, 2);
        partial += __shfl_xor_sync(0xFFFFFFFFu, partial, 1);
        if (p == 0) sc_sh[h][k] = (rb >= 0) ? partial : -1e30f;
    }
    __syncwarp();

    // ---- softmax over 196 keys (per warp)
    float m = -1e30f;
    for (int k = lane; k < NKEY; k += 32) m = fmaxf(m, sc_sh[h][k]);
    #pragma unroll
    for (int o = 16; o; o >>= 1) m = fmaxf(m, __shfl_xor_sync(0xFFFFFFFFu, m, o));
    float lsum = 0.f;
    for (int k = lane; k < NKEY; k += 32) {
        float pe = __expf(sc_sh[h][k] - m);
        sc_sh[h][k] = pe;
        lsum += pe;
    }
    #pragma unroll
    for (int o = 16; o; o >>= 1) lsum += __shfl_xor_sync(0xFFFFFFFFu, lsum, o);
    __syncwarp();

    // ---- weighted V accumulation
    float4 acc = make_float4(0.f, 0.f, 0.f, 0.f);
    for (int it = 0; it < NKEY / 2; ++it) {
        int k  = it * 2 + grp;
        int rb = rb_sh[k];
        if (rb >= 0 && p < 12) {
            float pk = sc_sh[h][k];
            float4 vv = *(const float4*)(vh + ((size_t)h * Mkv + rb) * HDm + p * 4);
            acc.x += pk * vv.x; acc.y += pk * vv.y;
            acc.z += pk * vv.z; acc.w += pk * vv.w;
        }
    }
    acc.x += __shfl_xor_sync(0xFFFFFFFFu, acc.x, 16);
    acc.y += __shfl_xor_sync(0xFFFFFFFFu, acc.y, 16);
    acc.z += __shfl_xor_sync(0xFFFFFFFFu, acc.z, 16);
    acc.w += __shfl_xor_sync(0xFFFFFFFFu, acc.w, 16);

    if (grp == 0 && p < 12) {
        float inv = 1.f / lsum;
        float4 o = make_float4(acc.x * inv, acc.y * inv, acc.z * inv, acc.w * inv);
        *(float4*)(attn_out + n * Dm + h * HDm + p * 4) = o;
    }
}

// ---------------------------------------------------------------------------
// kernel_launch
// ---------------------------------------------------------------------------
extern "C" void kernel_launch(void* const* d_in, const int* in_sizes, int n_in,
                              void* d_out, int out_size) {
    const float* query  = (const float*)d_in[0];
    const int*   pos    = (const int*)d_in[1];
    const float* fm     = (const float*)d_in[3];
    const int*   shapes = (const int*)d_in[4];
    const float* nw     = (const float*)d_in[5];
    const float* nb     = (const float*)d_in[6];
    const float* w_q    = (const float*)d_in[7];
    const float* w_kv   = (const float*)d_in[8];
    const float* w_out  = (const float*)d_in[9];
    float* out = (float*)d_out;

    const int D  = Dm;
    const int NQ = in_sizes[0] / D;
    const int Bn = in_sizes[2] - 1;
    const int total = in_sizes[3] / (Bn * D);
    const int Mkv = Bn * total;

    float *xn, *qb, *qrp, *attn, *kvp, *khp, *vhp;
    cudaGetSymbolAddress((void**)&xn,   g_xn);
    cudaGetSymbolAddress((void**)&qb,   g_q);
    cudaGetSymbolAddress((void**)&qrp,  g_qr);
    cudaGetSymbolAddress((void**)&attn, g_attn);
    cudaGetSymbolAddress((void**)&kvp,  g_kv);
    cudaGetSymbolAddress((void**)&khp,  g_kh);
    cudaGetSymbolAddress((void**)&vhp,  g_vh);

    // 1. LayerNorm
    ln_kernel<<<NQ, Dm>>>(query, nw, nb, xn);

    // 2. q = xn @ w_q^T   (tf32)
    {
        dim3 grid(D / 64, (NQ + 127) / 128);
        gemm_tf32_kernel<<<grid, 256>>>(xn, w_q, nullptr, qb, NQ, D, D);
    }

    // 3. RoPE + scale on q
    rope_q_kernel<<<NQ, Dm>>>(qb, pos, qrp);

    // 4. kv_maps = fm @ w_kv^T   (tf32, the big one)
    {
        dim3 grid((2 * D) / 64, (Mkv + 127) / 128);
        gemm_tf32_kernel<<<grid, 256>>>(fm, w_kv, nullptr, kvp, Mkv, 2 * D, D);
    }

    // 5. per-cell RoPE on K + head-major relayout
    rope_kv_kernel<<<Mkv, Dm>>>(kvp, shapes, khp, vhp, Mkv, total);

    // 6. sparse neighborhood attention
    attn_kernel<<<NQ, 256>>>(qrp, pos, shapes, khp, vhp, attn, total, Mkv);

    // 7. out = attn @ w_out^T + residual   (tf32)
    {
        dim3 grid(D / 64, (NQ + 127) / 128);
        gemm_tf32_kernel<<<grid, 256>>>(attn, w_out, query, out, NQ, D, D);
    }
}

// round 4
// speedup vs baseline: 3.9467x; 1.4524x over previous
#include <cuda_runtime.h>
#include <cuda_bf16.h>
#include <cstdint>

// ---------------------------------------------------------------------------
// Constants fixed by the dataset:
//   N=1024 queries, B=4, D=384, NH=8, HD=48, HALF=24, NF=8, L=4, NS=7
//   total cells per batch = 5440, K(keys/query) = 196
// ---------------------------------------------------------------------------
#define Dm 384
#define NHm 8
#define HDm 48
#define HALFm 24
#define Lm 4
#define NKEY 196
#define MAXQ 1024
#define MAXROWS 21760   // B * total

// ---------------- device scratch (static; no cudaMalloc) -------------------
__device__ float g_xn[MAXQ * Dm];        // layernorm output
__device__ float g_q[MAXQ * Dm];         // q projection (fp32)
__device__ float g_qr[MAXQ * Dm];        // rotated+scaled q (fp32)
__device__ float g_attn[MAXQ * Dm];      // attention output
__device__ __nv_bfloat16 g_kh[(size_t)NHm * MAXROWS * HDm];  // rotated K, head-major, bf16
__device__ __nv_bfloat16 g_vh[(size_t)NHm * MAXROWS * HDm];  // V, head-major, bf16

// ---------------------------------------------------------------------------
// LayerNorm: one block per query row, 384 threads
// ---------------------------------------------------------------------------
__global__ void ln_kernel(const float* __restrict__ x,
                          const float* __restrict__ w,
                          const float* __restrict__ b,
                          float* __restrict__ y) {
    int n = blockIdx.x;
    int d = threadIdx.x;
    float v = x[n * Dm + d];
    float s = v, s2 = v * v;
    #pragma unroll
    for (int o = 16; o; o >>= 1) {
        s  += __shfl_xor_sync(0xFFFFFFFFu, s,  o);
        s2 += __shfl_xor_sync(0xFFFFFFFFu, s2, o);
    }
    __shared__ float sw[12], sw2[12];
    int wid = d >> 5, lane = d & 31;
    if (lane == 0) { sw[wid] = s; sw2[wid] = s2; }
    __syncthreads();
    if (d == 0) {
        float a = 0.f, a2 = 0.f;
        #pragma unroll
        for (int i = 0; i < 12; i++) { a += sw[i]; a2 += sw2[i]; }
        sw[0] = a; sw2[0] = a2;
    }
    __syncthreads();
    float mu  = sw[0] * (1.f / Dm);
    float var = sw2[0] * (1.f / Dm) - mu * mu;
    float r = rsqrtf(var + 1e-5f);
    y[n * Dm + d] = (v - mu) * r * w[d] + b[d];
}

// ---------------------------------------------------------------------------
// bf16 tensor-core GEMM: C[m,n] = sum_k A[m,k]*W[n,k]
// CTA tile 128x96, K-step 32, 8 warps as 4(m) x 2(n), warp tile 32x48.
// mma m16n8k16 bf16 -> f32. Requires N%96==0, K%32==0; M guarded.
// mode 0: C fp32 (+R residual if non-null).
// mode 1: kv epilogue: first N/2 cols = K (RoPE-rotated), last N/2 = V;
//         written bf16 head-major into kh/vh.  Warp n-tile = 48 = one head,
//         so rotation pairs (d, d+24) are register-local (nt and nt+3).
// ---------------------------------------------------------------------------
__device__ __forceinline__ uint32_t pack_bf16x2(float lo, float hi) {
    uint32_t r;
    asm("cvt.rn.bf16x2.f32 %0, %1, %2;" : "=r"(r) : "f"(hi), "f"(lo));
    return r;
}

// smem layout: per row, 12 uint2 slots. Pair p (k=2p,2p+1) of k16-step ks
// lives at uint2 index ks*4 + (p&3), word (p>>2). So the fragment load
// (pairs tig and tig+4) is a single LDS.64.
__device__ __forceinline__ void store_tile_u2(uint2* sm, int row, int c4, float4 v) {
    uint32_t lo = pack_bf16x2(v.x, v.y);
    uint32_t hi = pack_bf16x2(v.z, v.w);
    int P  = c4 >> 1;                 // even pair index in [0,16)
    int ks = P >> 3;
    int p0 = P & 7, p1 = (P + 1) & 7; // same ks (P even)
    uint32_t* base = (uint32_t*)(sm + row * 12 + ks * 4);
    base[((p0 & 3) << 1) | (p0 >> 2)] = lo;
    base[((p1 & 3) << 1) | (p1 >> 2)] = hi;
}

__global__ void __launch_bounds__(256)
gemm_bf16_kernel(const float* __restrict__ A, const float* __restrict__ W,
                 const float* __restrict__ R, float* __restrict__ C,
                 __nv_bfloat16* __restrict__ kh, __nv_bfloat16* __restrict__ vh,
                 const int* __restrict__ shapes,
                 int M, int N, int K, int total, int mode) {
    __shared__ uint2 As[128 * 12];
    __shared__ uint2 Bs[96 * 12];
    __shared__ int sh_Ws[Lm], sh_off[Lm];

    const int tid  = threadIdx.x;
    const int lane = tid & 31;
    const int warp = tid >> 5;
    const int wm   = warp >> 1;   // 0..3
    const int wn   = warp & 1;    // 0..1
    const int bm   = blockIdx.y * 128;
    const int bn   = blockIdx.x * 96;
    const int tig  = lane & 3;
    const int gid  = lane >> 2;

    if (mode == 1 && tid == 0) {
        int off = 0;
        #pragma unroll
        for (int l = 0; l < Lm; l++) {
            int H = shapes[2 * l], Wl = shapes[2 * l + 1];
            sh_Ws[l] = Wl; sh_off[l] = off; off += H * Wl;
        }
    }

    float d[2][6][4];
    #pragma unroll
    for (int mt = 0; mt < 2; mt++)
        #pragma unroll
        for (int nt = 0; nt < 6; nt++)
            #pragma unroll
            for (int i = 0; i < 4; i++) d[mt][nt][i] = 0.f;

    float4 pa[4], pb[3];
    // prefetch first tile
    #pragma unroll
    for (int i = 0; i < 4; i++) {
        int idx = tid + 256 * i;
        int row = idx >> 3, c4 = (idx & 7) << 2;
        int gr = bm + row;
        pa[i] = (gr < M) ? *(const float4*)(A + (size_t)gr * K + c4)
                         : make_float4(0.f, 0.f, 0.f, 0.f);
    }
    #pragma unroll
    for (int i = 0; i < 3; i++) {
        int idx = tid + 256 * i;
        int row = idx >> 3, c4 = (idx & 7) << 2;
        pb[i] = *(const float4*)(W + (size_t)(bn + row) * K + c4);
    }

    for (int k0 = 0; k0 < K; k0 += 32) {
        #pragma unroll
        for (int i = 0; i < 4; i++) {
            int idx = tid + 256 * i;
            store_tile_u2(As, idx >> 3, (idx & 7) << 2, pa[i]);
        }
        #pragma unroll
        for (int i = 0; i < 3; i++) {
            int idx = tid + 256 * i;
            store_tile_u2(Bs, idx >> 3, (idx & 7) << 2, pb[i]);
        }
        __syncthreads();

        if (k0 + 32 < K) {
            #pragma unroll
            for (int i = 0; i < 4; i++) {
                int idx = tid + 256 * i;
                int row = idx >> 3, c4 = (idx & 7) << 2;
                int gr = bm + row;
                pa[i] = (gr < M) ? *(const float4*)(A + (size_t)gr * K + k0 + 32 + c4)
                                 : make_float4(0.f, 0.f, 0.f, 0.f);
            }
            #pragma unroll
            for (int i = 0; i < 3; i++) {
                int idx = tid + 256 * i;
                int row = idx >> 3, c4 = (idx & 7) << 2;
                pb[i] = *(const float4*)(W + (size_t)(bn + row) * K + k0 + 32 + c4);
            }
        }

        #pragma unroll
        for (int ks = 0; ks < 2; ks++) {
            uint2 ua[2][2];
            #pragma unroll
            for (int mt = 0; mt < 2; mt++) {
                int r = wm * 32 + mt * 16 + gid;
                ua[mt][0] = As[r * 12 + ks * 4 + tig];
                ua[mt][1] = As[(r + 8) * 12 + ks * 4 + tig];
            }
            uint2 ub[6];
            #pragma unroll
            for (int nt = 0; nt < 6; nt++) {
                int nn = wn * 48 + nt * 8 + gid;
                ub[nt] = Bs[nn * 12 + ks * 4 + tig];
            }
            #pragma unroll
            for (int mt = 0; mt < 2; mt++)
                #pragma unroll
                for (int nt = 0; nt < 6; nt++)
                    asm volatile(
                        "mma.sync.aligned.m16n8k16.row.col.f32.bf16.bf16.f32 "
                        "{%0,%1,%2,%3}, {%4,%5,%6,%7}, {%8,%9}, {%0,%1,%2,%3};"
                        : "+f"(d[mt][nt][0]), "+f"(d[mt][nt][1]),
                          "+f"(d[mt][nt][2]), "+f"(d[mt][nt][3])
                        : "r"(ua[mt][0].x), "r"(ua[mt][1].x),
                          "r"(ua[mt][0].y), "r"(ua[mt][1].y),
                          "r"(ub[nt].x), "r"(ub[nt].y));
        }
        __syncthreads();
    }

    // ------------------------------- epilogue -------------------------------
    if (mode == 0) {
        #pragma unroll
        for (int mt = 0; mt < 2; mt++)
            #pragma unroll
            for (int rh = 0; rh < 2; rh++) {
                int row = bm + wm * 32 + mt * 16 + gid + rh * 8;
                if (row >= M) continue;
                #pragma unroll
                for (int nt = 0; nt < 6; nt++) {
                    int col = bn + wn * 48 + nt * 8 + 2 * tig;
                    float2 o = make_float2(d[mt][nt][2 * rh], d[mt][nt][2 * rh + 1]);
                    if (R) {
                        float2 r2 = *(const float2*)(R + (size_t)row * N + col);
                        o.x += r2.x; o.y += r2.y;
                    }
                    *(float2*)(C + (size_t)row * N + col) = o;
                }
            }
        return;
    }

    // mode 1: kv epilogue (M == Mkv rows)
    const int half = N >> 1;                 // 384
    const bool isK = bn < half;
    const int h = (isK ? bn : bn - half) / HDm + wn;  // head index

    #pragma unroll
    for (int mt = 0; mt < 2; mt++) {
        #pragma unroll
        for (int rh = 0; rh < 2; rh++) {
            int row = bm + wm * 32 + mt * 16 + gid + rh * 8;
            if (row >= M) continue;
            size_t base = ((size_t)h * M + row) * HDm;
            if (isK) {
                // decode cell -> (i, j, l)
                int cell = row % total;
                int l = 0;
                #pragma unroll
                for (int q = 1; q < Lm; q++) if (cell >= sh_off[q]) l = q;
                int rem = cell - sh_off[l];
                int Wl = sh_Ws[l];
                float fi = (float)(rem / Wl);
                float fj = (float)(rem % Wl);
                float fl = (float)l;
                #pragma unroll
                for (int nt = 0; nt < 3; nt++) {
                    float o1[2], o2[2];
                    #pragma unroll
                    for (int i = 0; i < 2; i++) {
                        int jj = nt * 8 + 2 * tig + i;
                        float ang;
                        if (jj < 8)       ang = fi * exp10f(-(float)jj * 0.125f);
                        else if (jj < 16) ang = fj * exp10f(-(float)(jj - 8) * 0.125f);
                        else              ang = fl * exp10f((float)(jj - 16) * 0.125f);
                        float s, c;
                        sincosf(ang, &s, &c);
                        float x1 = d[mt][nt][2 * rh + i];
                        float x2 = d[mt][nt + 3][2 * rh + i];
                        o1[i] = x1 * c - x2 * s;
                        o2[i] = x1 * s + x2 * c;
                    }
                    int dlo = nt * 8 + 2 * tig;
                    *(uint32_t*)(kh + base + dlo)      = pack_bf16x2(o1[0], o1[1]);
                    *(uint32_t*)(kh + base + dlo + HALFm) = pack_bf16x2(o2[0], o2[1]);
                }
            } else {
                #pragma unroll
                for (int nt = 0; nt < 6; nt++) {
                    int dd = nt * 8 + 2 * tig;
                    *(uint32_t*)(vh + base + dd) =
                        pack_bf16x2(d[mt][nt][2 * rh], d[mt][nt][2 * rh + 1]);
                }
            }
        }
    }
}

// ---------------------------------------------------------------------------
// RoPE + scale for q: one block per query, 384 threads
// ---------------------------------------------------------------------------
__global__ void rope_q_kernel(const float* __restrict__ q,
                              const int* __restrict__ pos,
                              float* __restrict__ qr) {
    int n = blockIdx.x;
    int o = threadIdx.x;
    int h = o / HDm;
    int d = o - h * HDm;
    int j = (d < HALFm) ? d : d - HALFm;
    float fqi = (float)pos[n * 4 + 1];
    float fqj = (float)pos[n * 4 + 2];
    float fql = (float)pos[n * 4 + 3];
    float ang;
    if (j < 8)       ang = fqi * exp10f(-(float)j * 0.125f);
    else if (j < 16) ang = fqj * exp10f(-(float)(j - 8) * 0.125f);
    else             ang = fql * exp10f((float)(j - 16) * 0.125f);
    float s, c;
    sincosf(ang, &s, &c);
    float x1 = q[n * Dm + h * HDm + j];
    float x2 = q[n * Dm + h * HDm + HALFm + j];
    const float scale = 0.14433756729740643f;   // 1/sqrt(48)
    float r = (d < HALFm) ? (x1 * c - x2 * s) : (x1 * s + x2 * c);
    qr[n * Dm + o] = r * scale;
}

// ---------------------------------------------------------------------------
// Attention: one block per query, 8 warps (warp = head).
// 16-lane groups, 12 active lanes x uint2 (4 bf16) = 96B coalesced per key.
// ---------------------------------------------------------------------------
__global__ void __launch_bounds__(256)
attn_kernel(const float* __restrict__ qr,
            const int* __restrict__ pos,
            const int* __restrict__ shapes,
            const __nv_bfloat16* __restrict__ kh,
            const __nv_bfloat16* __restrict__ vh,
            float* __restrict__ attn_out,
            int total, int Mkv) {
    __shared__ float sc_sh[NHm][NKEY];
    __shared__ int   rb_sh[NKEY];
    __shared__ int   ci_sh[Lm], cj_sh[Lm], Hs_sh[Lm], Ws_sh[Lm], offs_sh[Lm];

    const int n = blockIdx.x;
    const int t = threadIdx.x;

    if (t == 0) {
        int qi = pos[n * 4 + 1], qj = pos[n * 4 + 2], ql = pos[n * 4 + 3];
        float Hq = (float)shapes[2 * ql];
        float Wq = (float)shapes[2 * ql + 1];
        int off = 0;
        #pragma unroll
        for (int l = 0; l < Lm; l++) {
            int H = shapes[2 * l], W = shapes[2 * l + 1];
            Hs_sh[l] = H; Ws_sh[l] = W; offs_sh[l] = off; off += H * W;
            ci_sh[l] = (int)floorf(((float)qi + 0.5f) * (float)H / Hq);
            cj_sh[l] = (int)floorf(((float)qj + 0.5f) * (float)W / Wq);
        }
    }
    __syncthreads();

    const int bq = pos[n * 4 + 0];
    if (t < NKEY) {
        int l  = t / 49;
        int rr = t - l * 49;
        int si = rr / 7, sj = rr - (rr / 7) * 7;
        int H = Hs_sh[l], W = Ws_sh[l];
        int ii = ci_sh[l] + si - 3;
        int jj = cj_sh[l] + sj - 3;
        bool vld = (ii >= 0) && (ii < H) && (jj >= 0) && (jj < W);
        rb_sh[t] = vld ? (bq * total + offs_sh[l] + ii * W + jj) : -1;
    }
    __syncthreads();

    const int h    = t >> 5;
    const int lane = t & 31;
    const int grp  = lane >> 4;      // 0 or 1
    const int p    = lane & 15;      // active if p < 12

    float4 q4 = make_float4(0.f, 0.f, 0.f, 0.f);
    if (p < 12) q4 = *(const float4*)(qr + n * Dm + h * HDm + p * 4);

    // ---- scores
    for (int it = 0; it < NKEY / 2; ++it) {
        int k  = it * 2 + grp;
        int rb = rb_sh[k];
        float partial = 0.f;
        if (p < 12 && rb >= 0) {
            uint2 kk = *(const uint2*)(kh + ((size_t)h * Mkv + rb) * HDm + p * 4);
            float2 f0 = __bfloat1622float2(*(const __nv_bfloat162*)&kk.x);
            float2 f1 = __bfloat1622float2(*(const __nv_bfloat162*)&kk.y);
            partial = q4.x * f0.x + q4.y * f0.y + q4.z * f1.x + q4.w * f1.y;
        }
        partial += __shfl_xor_sync(0xFFFFFFFFu, partial, 8);
        partial += __shfl_xor_sync(0xFFFFFFFFu, partial, 4);
        partial += __shfl_xor_sync(0xFFFFFFFFu, partial, 2);
        partial += __shfl_xor_sync(0xFFFFFFFFu, partial, 1);
        if (p == 0) sc_sh[h][k] = (rb >= 0) ? partial : -1e30f;
    }
    __syncwarp();

    // ---- softmax over 196 keys (per warp)
    float m = -1e30f;
    for (int k = lane; k < NKEY; k += 32) m = fmaxf(m, sc_sh[h][k]);
    #pragma unroll
    for (int o = 16; o; o >>= 1) m = fmaxf(m, __shfl_xor_sync(0xFFFFFFFFu, m, o));
    float lsum = 0.f;
    for (int k = lane; k < NKEY; k += 32) {
        float pe = __expf(sc_sh[h][k] - m);
        sc_sh[h][k] = pe;
        lsum += pe;
    }
    #pragma unroll
    for (int o = 16; o; o >>= 1) lsum += __shfl_xor_sync(0xFFFFFFFFu, lsum, o);
    __syncwarp();

    // ---- weighted V accumulation
    float4 acc = make_float4(0.f, 0.f, 0.f, 0.f);
    for (int it = 0; it < NKEY / 2; ++it) {
        int k  = it * 2 + grp;
        int rb = rb_sh[k];
        if (rb >= 0 && p < 12) {
            float pk = sc_sh[h][k];
            uint2 vv = *(const uint2*)(vh + ((size_t)h * Mkv + rb) * HDm + p * 4);
            float2 f0 = __bfloat1622float2(*(const __nv_bfloat162*)&vv.x);
            float2 f1 = __bfloat1622float2(*(const __nv_bfloat162*)&vv.y);
            acc.x += pk * f0.x; acc.y += pk * f0.y;
            acc.z += pk * f1.x; acc.w += pk * f1.y;
        }
    }
    acc.x += __shfl_xor_sync(0xFFFFFFFFu, acc.x, 16);
    acc.y += __shfl_xor_sync(0xFFFFFFFFu, acc.y, 16);
    acc.z += __shfl_xor_sync(0xFFFFFFFFu, acc.z, 16);
    acc.w += __shfl_xor_sync(0xFFFFFFFFu, acc.w, 16);

    if (grp == 0 && p < 12) {
        float inv = 1.f / lsum;
        float4 o = make_float4(acc.x * inv, acc.y * inv, acc.z * inv, acc.w * inv);
        *(float4*)(attn_out + n * Dm + h * HDm + p * 4) = o;
    }
}

// ---------------------------------------------------------------------------
// kernel_launch
// ---------------------------------------------------------------------------
extern "C" void kernel_launch(void* const* d_in, const int* in_sizes, int n_in,
                              void* d_out, int out_size) {
    const float* query  = (const float*)d_in[0];
    const int*   pos    = (const int*)d_in[1];
    const float* fm     = (const float*)d_in[3];
    const int*   shapes = (const int*)d_in[4];
    const float* nw     = (const float*)d_in[5];
    const float* nb     = (const float*)d_in[6];
    const float* w_q    = (const float*)d_in[7];
    const float* w_kv   = (const float*)d_in[8];
    const float* w_out  = (const float*)d_in[9];
    float* out = (float*)d_out;

    const int D  = Dm;
    const int NQ = in_sizes[0] / D;
    const int Bn = in_sizes[2] - 1;
    const int total = in_sizes[3] / (Bn * D);
    const int Mkv = Bn * total;

    float *xn, *qb, *qrp, *attn;
    __nv_bfloat16 *khp, *vhp;
    cudaGetSymbolAddress((void**)&xn,   g_xn);
    cudaGetSymbolAddress((void**)&qb,   g_q);
    cudaGetSymbolAddress((void**)&qrp,  g_qr);
    cudaGetSymbolAddress((void**)&attn, g_attn);
    cudaGetSymbolAddress((void**)&khp,  g_kh);
    cudaGetSymbolAddress((void**)&vhp,  g_vh);

    // 1. LayerNorm
    ln_kernel<<<NQ, Dm>>>(query, nw, nb, xn);

    // 2. q = xn @ w_q^T  (bf16 MMA, fp32 out)
    {
        dim3 grid(D / 96, (NQ + 127) / 128);
        gemm_bf16_kernel<<<grid, 256>>>(xn, w_q, nullptr, qb,
                                        nullptr, nullptr, nullptr,
                                        NQ, D, D, 0, 0);
    }

    // 3. RoPE + scale on q
    rope_q_kernel<<<NQ, Dm>>>(qb, pos, qrp);

    // 4. kv = fm @ w_kv^T  fused with K-RoPE + head-major bf16 relayout
    {
        dim3 grid((2 * D) / 96, (Mkv + 127) / 128);
        gemm_bf16_kernel<<<grid, 256>>>(fm, w_kv, nullptr, nullptr,
                                        khp, vhp, shapes,
                                        Mkv, 2 * D, D, total, 1);
    }

    // 5. sparse neighborhood attention
    attn_kernel<<<NQ, 256>>>(qrp, pos, shapes, khp, vhp, attn, total, Mkv);

    // 6. out = attn @ w_out^T + residual
    {
        dim3 grid(D / 96, (NQ + 127) / 128);
        gemm_bf16_kernel<<<grid, 256>>>(attn, w_out, query, out,
                                        nullptr, nullptr, nullptr,
                                        NQ, D, D, 0, 0);
    }
}

// round 6
// speedup vs baseline: 3.9827x; 1.0091x over previous
#include <cuda_runtime.h>
#include <cuda_bf16.h>
#include <cstdint>

// ---------------------------------------------------------------------------
// Constants fixed by the dataset:
//   N=1024 queries, B=4, D=384, NH=8, HD=48, HALF=24, NF=8, L=4, NS=7
//   total cells per batch = 5440, K(keys/query) = 196, Mkv = 21760
// ---------------------------------------------------------------------------
#define Dm 384
#define NHm 8
#define HDm 48
#define HALFm 24
#define Lm 4
#define NKEY 196
#define MAXQ 1024
#define MAXROWS 21760

// ---------------- device scratch (static; no cudaMalloc) -------------------
__device__ float g_xn[MAXQ * Dm];        // layernorm output
__device__ float g_q[MAXQ * Dm];         // q projection (fp32)
__device__ float g_qr[MAXQ * Dm];        // rotated+scaled q (fp32)
__device__ float g_attn[MAXQ * Dm];      // attention output
__device__ __align__(16) __nv_bfloat16 g_kh[(size_t)NHm * MAXROWS * HDm];
__device__ __align__(16) __nv_bfloat16 g_vh[(size_t)NHm * MAXROWS * HDm];
__device__ float2 g_tab_s[128 * 8];      // cos/sin(pos * 10^(-f/8)), pos<128
__device__ float2 g_tab_l[4 * 8];        // cos/sin(lvl * 10^(+f/8))

// ---------------------------------------------------------------------------
__device__ __forceinline__ uint32_t pack_bf16x2(float lo, float hi) {
    uint32_t r;
    asm("cvt.rn.bf16x2.f32 %0, %1, %2;" : "=r"(r) : "f"(hi), "f"(lo));
    return r;
}

// ---------------------------------------------------------------------------
// RoPE cos/sin tables (built once per launch, ~1056 entries)
// ---------------------------------------------------------------------------
__global__ void tab_kernel(float2* __restrict__ tab_s, float2* __restrict__ tab_l) {
    int t = blockIdx.x * blockDim.x + threadIdx.x;
    if (t < 128 * 8) {
        int p = t >> 3, f = t & 7;
        float s, c;
        sincosf((float)p * exp10f(-(float)f * 0.125f), &s, &c);
        tab_s[t] = make_float2(c, s);
    } else if (t < 128 * 8 + 32) {
        int u = t - 1024;
        int l = u >> 3, f = u & 7;
        float s, c;
        sincosf((float)l * exp10f((float)f * 0.125f), &s, &c);
        tab_l[u] = make_float2(c, s);
    }
}

// ---------------------------------------------------------------------------
// LayerNorm: one block per query row, 384 threads
// ---------------------------------------------------------------------------
__global__ void ln_kernel(const float* __restrict__ x,
                          const float* __restrict__ w,
                          const float* __restrict__ b,
                          float* __restrict__ y) {
    int n = blockIdx.x;
    int d = threadIdx.x;
    float v = x[n * Dm + d];
    float s = v, s2 = v * v;
    #pragma unroll
    for (int o = 16; o; o >>= 1) {
        s  += __shfl_xor_sync(0xFFFFFFFFu, s,  o);
        s2 += __shfl_xor_sync(0xFFFFFFFFu, s2, o);
    }
    __shared__ float sw[12], sw2[12];
    int wid = d >> 5, lane = d & 31;
    if (lane == 0) { sw[wid] = s; sw2[wid] = s2; }
    __syncthreads();
    if (d == 0) {
        float a = 0.f, a2 = 0.f;
        #pragma unroll
        for (int i = 0; i < 12; i++) { a += sw[i]; a2 += sw2[i]; }
        sw[0] = a; sw2[0] = a2;
    }
    __syncthreads();
    float mu  = sw[0] * (1.f / Dm);
    float var = sw2[0] * (1.f / Dm) - mu * mu;
    float r = rsqrtf(var + 1e-5f);
    y[n * Dm + d] = (v - mu) * r * w[d] + b[d];
}

// ---------------------------------------------------------------------------
// bf16 tensor-core GEMM: C[m,n] = sum_k A[m,k]*W[n,k]
// CTA tile 128x96, K-step 32, 8 warps as 4(m) x 2(n), warp tile 32x48.
// mode 0: C fp32 (+R residual if non-null).
// mode 1: kv epilogue: first N/2 cols = K (table-RoPE-rotated), last N/2 = V;
//         written bf16 head-major into kh/vh. Warp n-tile = 48 = one head,
//         so rotation pairs (d, d+24) are register-local (nt and nt+3).
// ---------------------------------------------------------------------------
__device__ __forceinline__ void store_tile_u2(uint2* sm, int row, int c4, float4 v) {
    uint32_t lo = pack_bf16x2(v.x, v.y);
    uint32_t hi = pack_bf16x2(v.z, v.w);
    int P  = c4 >> 1;                 // even pair index in [0,16)
    int ks = P >> 3;
    int p0 = P & 7, p1 = (P + 1) & 7; // same ks (P even)
    uint32_t* base = (uint32_t*)(sm + row * 12 + ks * 4);
    base[((p0 & 3) << 1) | (p0 >> 2)] = lo;
    base[((p1 & 3) << 1) | (p1 >> 2)] = hi;
}

__global__ void __launch_bounds__(256)
gemm_bf16_kernel(const float* __restrict__ A, const float* __restrict__ W,
                 const float* __restrict__ R, float* __restrict__ C,
                 __nv_bfloat16* __restrict__ kh, __nv_bfloat16* __restrict__ vh,
                 const int* __restrict__ shapes,
                 const float2* __restrict__ tab_s, const float2* __restrict__ tab_l,
                 int M, int N, int K, int total, int mode) {
    __shared__ uint2 As[128 * 12];
    __shared__ uint2 Bs[96 * 12];
    __shared__ int sh_Ws[Lm], sh_off[Lm];

    const int tid  = threadIdx.x;
    const int lane = tid & 31;
    const int warp = tid >> 5;
    const int wm   = warp >> 1;   // 0..3
    const int wn   = warp & 1;    // 0..1
    const int bm   = blockIdx.y * 128;
    const int bn   = blockIdx.x * 96;
    const int tig  = lane & 3;
    const int gid  = lane >> 2;

    if (mode == 1 && tid == 0) {
        int off = 0;
        #pragma unroll
        for (int l = 0; l < Lm; l++) {
            int H = shapes[2 * l], Wl = shapes[2 * l + 1];
            sh_Ws[l] = Wl; sh_off[l] = off; off += H * Wl;
        }
    }

    float d[2][6][4];
    #pragma unroll
    for (int mt = 0; mt < 2; mt++)
        #pragma unroll
        for (int nt = 0; nt < 6; nt++)
            #pragma unroll
            for (int i = 0; i < 4; i++) d[mt][nt][i] = 0.f;

    float4 pa[4], pb[3];
    // prefetch first tile
    #pragma unroll
    for (int i = 0; i < 4; i++) {
        int idx = tid + 256 * i;
        int row = idx >> 3, c4 = (idx & 7) << 2;
        int gr = bm + row;
        pa[i] = (gr < M) ? *(const float4*)(A + (size_t)gr * K + c4)
                         : make_float4(0.f, 0.f, 0.f, 0.f);
    }
    #pragma unroll
    for (int i = 0; i < 3; i++) {
        int idx = tid + 256 * i;
        int row = idx >> 3, c4 = (idx & 7) << 2;
        pb[i] = *(const float4*)(W + (size_t)(bn + row) * K + c4);
    }

    for (int k0 = 0; k0 < K; k0 += 32) {
        #pragma unroll
        for (int i = 0; i < 4; i++) {
            int idx = tid + 256 * i;
            store_tile_u2(As, idx >> 3, (idx & 7) << 2, pa[i]);
        }
        #pragma unroll
        for (int i = 0; i < 3; i++) {
            int idx = tid + 256 * i;
            store_tile_u2(Bs, idx >> 3, (idx & 7) << 2, pb[i]);
        }
        __syncthreads();

        if (k0 + 32 < K) {
            #pragma unroll
            for (int i = 0; i < 4; i++) {
                int idx = tid + 256 * i;
                int row = idx >> 3, c4 = (idx & 7) << 2;
                int gr = bm + row;
                pa[i] = (gr < M) ? *(const float4*)(A + (size_t)gr * K + k0 + 32 + c4)
                                 : make_float4(0.f, 0.f, 0.f, 0.f);
            }
            #pragma unroll
            for (int i = 0; i < 3; i++) {
                int idx = tid + 256 * i;
                int row = idx >> 3, c4 = (idx & 7) << 2;
                pb[i] = *(const float4*)(W + (size_t)(bn + row) * K + k0 + 32 + c4);
            }
        }

        #pragma unroll
        for (int ks = 0; ks < 2; ks++) {
            uint2 ua[2][2];
            #pragma unroll
            for (int mt = 0; mt < 2; mt++) {
                int r = wm * 32 + mt * 16 + gid;
                ua[mt][0] = As[r * 12 + ks * 4 + tig];
                ua[mt][1] = As[(r + 8) * 12 + ks * 4 + tig];
            }
            uint2 ub[6];
            #pragma unroll
            for (int nt = 0; nt < 6; nt++) {
                int nn = wn * 48 + nt * 8 + gid;
                ub[nt] = Bs[nn * 12 + ks * 4 + tig];
            }
            #pragma unroll
            for (int mt = 0; mt < 2; mt++)
                #pragma unroll
                for (int nt = 0; nt < 6; nt++)
                    asm volatile(
                        "mma.sync.aligned.m16n8k16.row.col.f32.bf16.bf16.f32 "
                        "{%0,%1,%2,%3}, {%4,%5,%6,%7}, {%8,%9}, {%0,%1,%2,%3};"
                        : "+f"(d[mt][nt][0]), "+f"(d[mt][nt][1]),
                          "+f"(d[mt][nt][2]), "+f"(d[mt][nt][3])
                        : "r"(ua[mt][0].x), "r"(ua[mt][1].x),
                          "r"(ua[mt][0].y), "r"(ua[mt][1].y),
                          "r"(ub[nt].x), "r"(ub[nt].y));
        }
        __syncthreads();
    }

    // ------------------------------- epilogue -------------------------------
    if (mode == 0) {
        #pragma unroll
        for (int mt = 0; mt < 2; mt++)
            #pragma unroll
            for (int rh = 0; rh < 2; rh++) {
                int row = bm + wm * 32 + mt * 16 + gid + rh * 8;
                if (row >= M) continue;
                #pragma unroll
                for (int nt = 0; nt < 6; nt++) {
                    int col = bn + wn * 48 + nt * 8 + 2 * tig;
                    float2 o = make_float2(d[mt][nt][2 * rh], d[mt][nt][2 * rh + 1]);
                    if (R) {
                        float2 r2 = *(const float2*)(R + (size_t)row * N + col);
                        o.x += r2.x; o.y += r2.y;
                    }
                    *(float2*)(C + (size_t)row * N + col) = o;
                }
            }
        return;
    }

    // mode 1: kv epilogue (M == Mkv rows), table-based RoPE
    const int half = N >> 1;                 // 384
    const bool isK = bn < half;
    const int h = (isK ? bn : bn - half) / HDm + wn;  // head index

    #pragma unroll
    for (int mt = 0; mt < 2; mt++) {
        #pragma unroll
        for (int rh = 0; rh < 2; rh++) {
            int row = bm + wm * 32 + mt * 16 + gid + rh * 8;
            if (row >= M) continue;
            size_t base = ((size_t)h * M + row) * HDm;
            if (isK) {
                // decode cell -> (icoord, jcoord, l)
                int cell = row % total;
                int l = 0;
                #pragma unroll
                for (int q = 1; q < Lm; q++) if (cell >= sh_off[q]) l = q;
                int rem = cell - sh_off[l];
                int Wl = sh_Ws[l];
                int ic = rem / Wl;
                int jc = rem - ic * Wl;
                #pragma unroll
                for (int nt = 0; nt < 3; nt++) {
                    float o1[2], o2[2];
                    #pragma unroll
                    for (int i = 0; i < 2; i++) {
                        int jdim = nt * 8 + 2 * tig + i;   // 0..23
                        float2 cs = (jdim < 8)  ? tab_s[ic * 8 + jdim]
                                  : (jdim < 16) ? tab_s[jc * 8 + jdim - 8]
                                                : tab_l[l * 8 + jdim - 16];
                        float x1 = d[mt][nt][2 * rh + i];
                        float x2 = d[mt][nt + 3][2 * rh + i];
                        o1[i] = x1 * cs.x - x2 * cs.y;
                        o2[i] = x1 * cs.y + x2 * cs.x;
                    }
                    int dlo = nt * 8 + 2 * tig;
                    *(uint32_t*)(kh + base + dlo)         = pack_bf16x2(o1[0], o1[1]);
                    *(uint32_t*)(kh + base + dlo + HALFm) = pack_bf16x2(o2[0], o2[1]);
                }
            } else {
                #pragma unroll
                for (int nt = 0; nt < 6; nt++) {
                    int dd = nt * 8 + 2 * tig;
                    *(uint32_t*)(vh + base + dd) =
                        pack_bf16x2(d[mt][nt][2 * rh], d[mt][nt][2 * rh + 1]);
                }
            }
        }
    }
}

// ---------------------------------------------------------------------------
// RoPE + scale for q (table-based): one block per query, 384 threads
// ---------------------------------------------------------------------------
__global__ void rope_q_kernel(const float* __restrict__ q,
                              const int* __restrict__ pos,
                              const float2* __restrict__ tab_s,
                              const float2* __restrict__ tab_l,
                              float* __restrict__ qr) {
    int n = blockIdx.x;
    int o = threadIdx.x;
    int h = o / HDm;
    int d = o - h * HDm;
    int j = (d < HALFm) ? d : d - HALFm;
    int qi = pos[n * 4 + 1], qj = pos[n * 4 + 2], ql = pos[n * 4 + 3];
    float2 cs = (j < 8)  ? tab_s[qi * 8 + j]
              : (j < 16) ? tab_s[qj * 8 + j - 8]
                         : tab_l[ql * 8 + j - 16];
    float x1 = q[n * Dm + h * HDm + j];
    float x2 = q[n * Dm + h * HDm + HALFm + j];
    const float scale = 0.14433756729740643f;   // 1/sqrt(48)
    float r = (d < HALFm) ? (x1 * cs.x - x2 * cs.y) : (x1 * cs.y + x2 * cs.x);
    qr[n * Dm + o] = r * scale;
}

// ---------------------------------------------------------------------------
// Attention: one block per query, 8 warps (warp = head), bf16 K/V.
// 16-lane groups, 12 active lanes x uint2 (4 bf16) = 96B coalesced per key.
// ---------------------------------------------------------------------------
__global__ void __launch_bounds__(256)
attn_kernel(const float* __restrict__ qr,
            const int* __restrict__ pos,
            const int* __restrict__ shapes,
            const __nv_bfloat16* __restrict__ kh,
            const __nv_bfloat16* __restrict__ vh,
            float* __restrict__ attn_out,
            int total, int Mkv) {
    __shared__ float sc_sh[NHm][NKEY];
    __shared__ int   rb_sh[NKEY];
    __shared__ int   ci_sh[Lm], cj_sh[Lm], Hs_sh[Lm], Ws_sh[Lm], offs_sh[Lm];

    const int n = blockIdx.x;
    const int t = threadIdx.x;

    if (t == 0) {
        int qi = pos[n * 4 + 1], qj = pos[n * 4 + 2], ql = pos[n * 4 + 3];
        float Hq = (float)shapes[2 * ql];
        float Wq = (float)shapes[2 * ql + 1];
        int off = 0;
        #pragma unroll
        for (int l = 0; l < Lm; l++) {
            int H = shapes[2 * l], W = shapes[2 * l + 1];
            Hs_sh[l] = H; Ws_sh[l] = W; offs_sh[l] = off; off += H * W;
            ci_sh[l] = (int)floorf(((float)qi + 0.5f) * (float)H / Hq);
            cj_sh[l] = (int)floorf(((float)qj + 0.5f) * (float)W / Wq);
        }
    }
    __syncthreads();

    const int bq = pos[n * 4 + 0];
    if (t < NKEY) {
        int l  = t / 49;
        int rr = t - l * 49;
        int si = rr / 7, sj = rr - (rr / 7) * 7;
        int H = Hs_sh[l], W = Ws_sh[l];
        int ii = ci_sh[l] + si - 3;
        int jj = cj_sh[l] + sj - 3;
        bool vld = (ii >= 0) && (ii < H) && (jj >= 0) && (jj < W);
        rb_sh[t] = vld ? (bq * total + offs_sh[l] + ii * W + jj) : -1;
    }
    __syncthreads();

    const int h    = t >> 5;
    const int lane = t & 31;
    const int grp  = lane >> 4;
    const int p    = lane & 15;

    float4 q4 = make_float4(0.f, 0.f, 0.f, 0.f);
    if (p < 12) q4 = *(const float4*)(qr + n * Dm + h * HDm + p * 4);

    for (int it = 0; it < NKEY / 2; ++it) {
        int k  = it * 2 + grp;
        int rb = rb_sh[k];
        float partial = 0.f;
        if (p < 12 && rb >= 0) {
            uint2 kk = *(const uint2*)(kh + ((size_t)h * Mkv + rb) * HDm + p * 4);
            float2 f0 = __bfloat1622float2(*(const __nv_bfloat162*)&kk.x);
            float2 f1 = __bfloat1622float2(*(const __nv_bfloat162*)&kk.y);
            partial = q4.x * f0.x + q4.y * f0.y + q4.z * f1.x + q4.w * f1.y;
        }
        partial += __shfl_xor_sync(0xFFFFFFFFu, partial, 8);
        partial += __shfl_xor_sync(0xFFFFFFFFu, partial, 4);
        partial += __shfl_xor_sync(0xFFFFFFFFu, partial, 2);
        partial += __shfl_xor_sync(0xFFFFFFFFu, partial, 1);
        if (p == 0) sc_sh[h][k] = (rb >= 0) ? partial : -1e30f;
    }
    __syncwarp();

    float m = -1e30f;
    for (int k = lane; k < NKEY; k += 32) m = fmaxf(m, sc_sh[h][k]);
    #pragma unroll
    for (int o = 16; o; o >>= 1) m = fmaxf(m, __shfl_xor_sync(0xFFFFFFFFu, m, o));
    float lsum = 0.f;
    for (int k = lane; k < NKEY; k += 32) {
        float pe = __expf(sc_sh[h][k] - m);
        sc_sh[h][k] = pe;
        lsum += pe;
    }
    #pragma unroll
    for (int o = 16; o; o >>= 1) lsum += __shfl_xor_sync(0xFFFFFFFFu, lsum, o);
    __syncwarp();

    float4 acc = make_float4(0.f, 0.f, 0.f, 0.f);
    for (int it = 0; it < NKEY / 2; ++it) {
        int k  = it * 2 + grp;
        int rb = rb_sh[k];
        if (rb >= 0 && p < 12) {
            float pk = sc_sh[h][k];
            uint2 vv = *(const uint2*)(vh + ((size_t)h * Mkv + rb) * HDm + p * 4);
            float2 f0 = __bfloat1622float2(*(const __nv_bfloat162*)&vv.x);
            float2 f1 = __bfloat1622float2(*(const __nv_bfloat162*)&vv.y);
            acc.x += pk * f0.x; acc.y += pk * f0.y;
            acc.z += pk * f1.x; acc.w += pk * f1.y;
        }
    }
    acc.x += __shfl_xor_sync(0xFFFFFFFFu, acc.x, 16);
    acc.y += __shfl_xor_sync(0xFFFFFFFFu, acc.y, 16);
    acc.z += __shfl_xor_sync(0xFFFFFFFFu, acc.z, 16);
    acc.w += __shfl_xor_sync(0xFFFFFFFFu, acc.w, 16);

    if (grp == 0 && p < 12) {
        float inv = 1.f / lsum;
        float4 o = make_float4(acc.x * inv, acc.y * inv, acc.z * inv, acc.w * inv);
        *(float4*)(attn_out + n * Dm + h * HDm + p * 4) = o;
    }
}

// ---------------------------------------------------------------------------
// kernel_launch
// ---------------------------------------------------------------------------
extern "C" void kernel_launch(void* const* d_in, const int* in_sizes, int n_in,
                              void* d_out, int out_size) {
    const float* query  = (const float*)d_in[0];
    const int*   pos    = (const int*)d_in[1];
    const float* fm     = (const float*)d_in[3];
    const int*   shapes = (const int*)d_in[4];
    const float* nw     = (const float*)d_in[5];
    const float* nb     = (const float*)d_in[6];
    const float* w_q    = (const float*)d_in[7];
    const float* w_kv   = (const float*)d_in[8];
    const float* w_out  = (const float*)d_in[9];
    float* out = (float*)d_out;

    const int D  = Dm;
    const int NQ = in_sizes[0] / D;
    const int Bn = in_sizes[2] - 1;
    const int total = in_sizes[3] / (Bn * D);
    const int Mkv = Bn * total;

    float *xn, *qb, *qrp, *attn;
    __nv_bfloat16 *khp, *vhp;
    float2 *tabs, *tabl;
    cudaGetSymbolAddress((void**)&xn,   g_xn);
    cudaGetSymbolAddress((void**)&qb,   g_q);
    cudaGetSymbolAddress((void**)&qrp,  g_qr);
    cudaGetSymbolAddress((void**)&attn, g_attn);
    cudaGetSymbolAddress((void**)&khp,  g_kh);
    cudaGetSymbolAddress((void**)&vhp,  g_vh);
    cudaGetSymbolAddress((void**)&tabs, g_tab_s);
    cudaGetSymbolAddress((void**)&tabl, g_tab_l);

    // 0. RoPE tables
    tab_kernel<<<3, 384>>>(tabs, tabl);

    // 1. LayerNorm
    ln_kernel<<<NQ, Dm>>>(query, nw, nb, xn);

    // 2. q = xn @ w_q^T  (bf16 MMA, fp32 out)
    {
        dim3 grid(D / 96, (NQ + 127) / 128);
        gemm_bf16_kernel<<<grid, 256>>>(xn, w_q, nullptr, qb,
                                        nullptr, nullptr, nullptr, tabs, tabl,
                                        NQ, D, D, 0, 0);
    }

    // 3. RoPE + scale on q (tables)
    rope_q_kernel<<<NQ, Dm>>>(qb, pos, tabs, tabl, qrp);

    // 4. kv = fm @ w_kv^T fused with table-RoPE(K) + head-major bf16 relayout
    {
        dim3 grid((2 * D) / 96, (Mkv + 127) / 128);
        gemm_bf16_kernel<<<grid, 256>>>(fm, w_kv, nullptr, nullptr,
                                        khp, vhp, shapes, tabs, tabl,
                                        Mkv, 2 * D, D, total, 1);
    }

    // 5. sparse neighborhood attention
    attn_kernel<<<NQ, 256>>>(qrp, pos, shapes, khp, vhp, attn, total, Mkv);

    // 6. out = attn @ w_out^T + residual
    {
        dim3 grid(D / 96, (NQ + 127) / 128);
        gemm_bf16_kernel<<<grid, 256>>>(attn, w_out, query, out,
                                        nullptr, nullptr, nullptr, tabs, tabl,
                                        NQ, D, D, 0, 0);
    }
}